// round 11
// baseline (speedup 1.0000x reference)
#include <cuda_runtime.h>
#include <cuda_bf16.h>
#include <cstdint>

// Problem constants: N=100000 nodes, E=1600000 edges, D=128, L=4
#define DNN   128
#define MAXN  100000
#define MAXE  1600000
#define EPS   1e-5f

// Static device scratch (no cudaMalloc anywhere)
__device__ float    g_h0 [(size_t)MAXN * DNN];
__device__ float    g_h1 [(size_t)MAXN * DNN];
__device__ int      g_deg   [MAXN + 1];
__device__ int      g_off   [MAXN + 1];
__device__ int      g_cursor[MAXN + 1];
__device__ int      g_esrc  [MAXE];
// Pre-split weights: [4 layers][128 k-pairs][136 cols] packed bf16x2 (hi & lo)
#define WPSTRIDE 136
__device__ uint32_t g_whi[4 * 128 * WPSTRIDE];
__device__ uint32_t g_wlo[4 * 128 * WPSTRIDE];

// ---------------------------------------------------------------------------
// bf16 split: x ~= hi + lo. pack2: element a (even k) LOW half, b HIGH half.
// ---------------------------------------------------------------------------
__device__ __forceinline__ void bfsplit2(float a, float b,
                                         uint32_t& hi, uint32_t& lo)
{
    __nv_bfloat16 ah = __float2bfloat16(a);
    __nv_bfloat16 bh = __float2bfloat16(b);
    float ar = a - __bfloat162float(ah);
    float br = b - __bfloat162float(bh);
    __nv_bfloat16 al = __float2bfloat16(ar);
    __nv_bfloat16 bl = __float2bfloat16(br);
    hi = ((uint32_t)__bfloat16_as_ushort(bh) << 16) | __bfloat16_as_ushort(ah);
    lo = ((uint32_t)__bfloat16_as_ushort(bl) << 16) | __bfloat16_as_ushort(al);
}

// ---------------------------------------------------------------------------
// W pre-split: stacked K layout [W_rel(128) ; W_root(128)] per layer,
// packed along k into bf16x2 pairs. One thread per packed word.
// ---------------------------------------------------------------------------
__global__ __launch_bounds__(256)
void wsplit_kernel(const float* __restrict__ Wrel,
                   const float* __restrict__ Wroot,
                   uint32_t* __restrict__ whi,
                   uint32_t* __restrict__ wlo)
{
    int idx = blockIdx.x * 256 + threadIdx.x;     // 0 .. 4*128*128-1
    if (idx >= 4 * 128 * 128) return;
    int c = idx & 127;
    int p = (idx >> 7) & 127;                     // k-pair 0..127
    int l = idx >> 14;                            // layer

    int k0 = 2 * p;
    float v0, v1;
    if (p < 64) {                                 // both from W_rel
        v0 = Wrel[(size_t)l * 16384 + k0 * 128 + c];
        v1 = Wrel[(size_t)l * 16384 + (k0 + 1) * 128 + c];
    } else {                                      // both from W_root
        v0 = Wroot[(size_t)l * 16384 + (k0 - 128) * 128 + c];
        v1 = Wroot[(size_t)l * 16384 + (k0 - 127) * 128 + c];
    }
    uint32_t hi, lo;
    bfsplit2(v0, v1, hi, lo);
    size_t o = ((size_t)l * 128 + p) * WPSTRIDE + c;
    whi[o] = hi;
    wlo[o] = lo;
}

// ---------------------------------------------------------------------------
// CSR build: histogram of dst -> exclusive scan -> reorder src by dst bucket.
// ---------------------------------------------------------------------------
__global__ __launch_bounds__(256)
void hist_kernel(const int* __restrict__ dst, int* __restrict__ deg, int E)
{
    int e = blockIdx.x * blockDim.x + threadIdx.x;
    if (e < E) atomicAdd(&deg[dst[e]], 1);
}

__global__ __launch_bounds__(1024)
void scan_kernel(const int* __restrict__ deg, int* __restrict__ off,
                 int* __restrict__ cur, int Nn, int E)
{
    __shared__ int part[1024];
    const int tid   = threadIdx.x;
    const int chunk = (Nn + 1023) / 1024;
    const int s0    = tid * chunk;
    const int s1    = min(s0 + chunk, Nn);

    int sum = 0;
    for (int i = s0; i < s1; i++) sum += deg[i];
    part[tid] = sum;
    __syncthreads();

    for (int stp = 1; stp < 1024; stp <<= 1) {
        int v = (tid >= stp) ? part[tid - stp] : 0;
        __syncthreads();
        part[tid] += v;
        __syncthreads();
    }
    int base = (tid == 0) ? 0 : part[tid - 1];

    for (int i = s0; i < s1; i++) {
        off[i] = base;
        cur[i] = base;
        base  += deg[i];
    }
    if (tid == 0) off[Nn] = E;
}

__global__ __launch_bounds__(256)
void reorder_kernel(const int* __restrict__ src, const int* __restrict__ dst,
                    int* __restrict__ cur, int* __restrict__ esrc, int E)
{
    int e = blockIdx.x * blockDim.x + threadIdx.x;
    if (e >= E) return;
    int pos = atomicAdd(&cur[dst[e]], 1);
    esrc[pos] = src[e];
}

// ---------------------------------------------------------------------------
// bf16 m16n8k16 MMA (A row-major, B col-major, f32 accum) — sm_90+ legacy path
// ---------------------------------------------------------------------------
#define MMA_BF16(d, a, b)                                                     \
    asm volatile(                                                             \
        "mma.sync.aligned.m16n8k16.row.col.f32.bf16.bf16.f32 "                \
        "{%0,%1,%2,%3},{%4,%5,%6,%7},{%8,%9},{%0,%1,%2,%3};"                  \
        : "+f"((d)[0]), "+f"((d)[1]), "+f"((d)[2]), "+f"((d)[3])              \
        : "r"((a)[0]), "r"((a)[1]), "r"((a)[2]), "r"((a)[3]),                 \
          "r"((b)[0]), "r"((b)[1]))

// Dynamic SMEM layout (word offsets):
//   XH[64][132]  (8448 w)   X packed hi, full K (128 kpairs) + pad 4
//   XL[64][132]  (8448 w)
//   WH[32][136]  (4352 w)   W chunk (one kt), stride 136
//   WL[32][136]  (4352 w)
#define XH_OFF 0
#define XL_OFF 8448
#define WH_OFF 16896
#define WL_OFF 21248
#define CONV_SMEM ((21248 + 4352) * 4)    // 102400 bytes

// ---------------------------------------------------------------------------
// Fused gather + conv layer.
// Phase A: each warp aggregates 8 nodes (CSR walk) + loads own h row; splits
//          both into bf16 hi/lo and stores the full-K X tile (64 x 256).
// Phase B: R8 mma.sync 3-pass compensated core; W chunk reloaded per kt.
// MODE 0: relu->LN   MODE 1: +h->relu->LN   MODE 2: plain
// ---------------------------------------------------------------------------
template <int MODE>
__global__ __launch_bounds__(256)
void conv_fused(const float* __restrict__ hin,
                const int* __restrict__ esrc,
                const int* __restrict__ off,
                const uint32_t* __restrict__ whi,  // layer slice [128][136]
                const uint32_t* __restrict__ wlo,
                const float* __restrict__ br,
                const float* __restrict__ gamma,
                const float* __restrict__ beta,
                float* __restrict__ out,
                int Nn)
{
    extern __shared__ uint32_t sm[];
    uint32_t* XH = sm + XH_OFF;
    uint32_t* XL = sm + XL_OFF;
    uint32_t* WH = sm + WH_OFF;
    uint32_t* WL = sm + WL_OFF;
    float (*ob)[132] = reinterpret_cast<float(*)[132]>(sm);   // epilogue overlay

    const int tid  = threadIdx.x;
    const int lane = tid & 31;
    const int wid  = tid >> 5;
    const int wr   = wid >> 2;       // warp row: 0..1
    const int wc   = wid & 3;        // warp col: 0..3
    const int rowBase = blockIdx.x * 64;
    const int qr = lane >> 2;        // 0..7
    const int qc = lane & 3;         // 0..3

    // ================= Phase A: gather + split into SMEM X =================
    for (int i = 0; i < 8; i++) {
        int row  = wid * 8 + i;
        int node = rowBase + row;
        float4 a  = make_float4(0.f, 0.f, 0.f, 0.f);
        float4 hv = make_float4(0.f, 0.f, 0.f, 0.f);
        if (node < Nn) {
            int b = off[node];
            int e = off[node + 1];
            int s = (b < e) ? esrc[b] : 0;
            for (int j = b; j < e; j++) {
                int snxt = (j + 1 < e) ? esrc[j + 1] : 0;
                float4 v = reinterpret_cast<const float4*>(
                    hin + (size_t)s * DNN)[lane];
                a.x += v.x; a.y += v.y; a.z += v.z; a.w += v.w;
                s = snxt;
            }
            hv = reinterpret_cast<const float4*>(hin + (size_t)node * DNN)[lane];
        }
        uint32_t h0, l0, h1, l1;
        // agg half: k 0..127 -> kpairs 0..63 (lane covers kpairs 2*lane, +1)
        bfsplit2(a.x, a.y, h0, l0);
        bfsplit2(a.z, a.w, h1, l1);
        *reinterpret_cast<uint2*>(&XH[row * 132 + lane * 2]) = make_uint2(h0, h1);
        *reinterpret_cast<uint2*>(&XL[row * 132 + lane * 2]) = make_uint2(l0, l1);
        // root half: k 128..255 -> kpairs 64..127
        bfsplit2(hv.x, hv.y, h0, l0);
        bfsplit2(hv.z, hv.w, h1, l1);
        *reinterpret_cast<uint2*>(&XH[row * 132 + 64 + lane * 2]) = make_uint2(h0, h1);
        *reinterpret_cast<uint2*>(&XL[row * 132 + 64 + lane * 2]) = make_uint2(l0, l1);
    }
    __syncthreads();

    // ================= Phase B: 3-pass compensated MMA =====================
    float acc[2][4][4];
#pragma unroll
    for (int m = 0; m < 2; m++)
#pragma unroll
        for (int n = 0; n < 4; n++)
#pragma unroll
            for (int j = 0; j < 4; j++) acc[m][n][j] = 0.0f;

    for (int kt = 0; kt < 4; kt++) {
        // ---- load W chunk kt (32 kpairs x 128 cols), pre-split global ----
#pragma unroll
        for (int p = 0; p < 4; p++) {
            int q  = tid + p * 256;           // 0..1023
            int kp = q >> 5;                  // 0..31
            int c4 = (q & 31) * 4;            // 0..124
            size_t go = (size_t)(kt * 32 + kp) * WPSTRIDE + c4;
            *reinterpret_cast<uint4*>(&WH[kp * 136 + c4]) =
                *reinterpret_cast<const uint4*>(whi + go);
            *reinterpret_cast<uint4*>(&WL[kp * 136 + c4]) =
                *reinterpret_cast<const uint4*>(wlo + go);
        }
        __syncthreads();

#pragma unroll
        for (int ks = 0; ks < 4; ks++) {
            const int kpx = kt * 32 + ks * 8;   // X kpair base (global)
            const int kpw = ks * 8;             // W kpair base (chunk-local)

            uint32_t Ah[2][4], Al[2][4], Bh[4][2], Bl[4][2];
#pragma unroll
            for (int m = 0; m < 2; m++) {
                int r = wr * 32 + m * 16 + qr;
                Ah[m][0] = XH[ r      * 132 + kpx + qc    ];
                Ah[m][1] = XH[(r + 8) * 132 + kpx + qc    ];
                Ah[m][2] = XH[ r      * 132 + kpx + qc + 4];
                Ah[m][3] = XH[(r + 8) * 132 + kpx + qc + 4];
                Al[m][0] = XL[ r      * 132 + kpx + qc    ];
                Al[m][1] = XL[(r + 8) * 132 + kpx + qc    ];
                Al[m][2] = XL[ r      * 132 + kpx + qc + 4];
                Al[m][3] = XL[(r + 8) * 132 + kpx + qc + 4];
            }
#pragma unroll
            for (int n = 0; n < 4; n++) {
                int col = wc * 32 + n * 8 + qr;
                Bh[n][0] = WH[(kpw + qc    ) * 136 + col];
                Bh[n][1] = WH[(kpw + qc + 4) * 136 + col];
                Bl[n][0] = WL[(kpw + qc    ) * 136 + col];
                Bl[n][1] = WL[(kpw + qc + 4) * 136 + col];
            }

#pragma unroll
            for (int m = 0; m < 2; m++)
#pragma unroll
                for (int n = 0; n < 4; n++) {
                    MMA_BF16(acc[m][n], Ah[m], Bh[n]);
                    MMA_BF16(acc[m][n], Ah[m], Bl[n]);
                    MMA_BF16(acc[m][n], Al[m], Bh[n]);
                }
        }
        __syncthreads();   // before next kt overwrites W (and final: before ob)
    }

    // ================= Epilogue: acc -> smem overlay, per-row LN ===========
#pragma unroll
    for (int m = 0; m < 2; m++) {
        int r0 = wr * 32 + m * 16 + qr;
#pragma unroll
        for (int n = 0; n < 4; n++) {
            int c = wc * 32 + n * 8 + qc * 2;
            ob[r0    ][c    ] = acc[m][n][0];
            ob[r0    ][c + 1] = acc[m][n][1];
            ob[r0 + 8][c    ] = acc[m][n][2];
            ob[r0 + 8][c + 1] = acc[m][n][3];
        }
    }
    __syncthreads();

    // Warp wid handles rows wid*8 .. wid*8+7; lane holds 4 cols (lane*4).
    const int c0 = lane * 4;
    const float4 bv = *reinterpret_cast<const float4*>(br + c0);
    float4 gv, btv;
    if (MODE < 2) {
        gv  = *reinterpret_cast<const float4*>(gamma + c0);
        btv = *reinterpret_cast<const float4*>(beta  + c0);
    }

#pragma unroll
    for (int i = 0; i < 8; i++) {
        int lr = wid * 8 + i;
        int r  = rowBase + lr;
        bool valid = (r < Nn);

        float4 v = *reinterpret_cast<const float4*>(&ob[lr][c0]);
        float v0 = v.x + bv.x;
        float v1 = v.y + bv.y;
        float v2 = v.z + bv.z;
        float v3 = v.w + bv.w;

        if (MODE == 1) {
            if (valid) {
                float4 hr = *reinterpret_cast<const float4*>(
                    hin + (size_t)r * DNN + c0);
                v0 += hr.x; v1 += hr.y; v2 += hr.z; v3 += hr.w;
            }
        }

        if (MODE < 2) {
            v0 = fmaxf(v0, 0.0f);
            v1 = fmaxf(v1, 0.0f);
            v2 = fmaxf(v2, 0.0f);
            v3 = fmaxf(v3, 0.0f);

            float su = v0 + v1 + v2 + v3;
            float s2 = v0 * v0 + v1 * v1 + v2 * v2 + v3 * v3;
#pragma unroll
            for (int o = 16; o >= 1; o >>= 1) {
                su += __shfl_xor_sync(0xFFFFFFFFu, su, o);
                s2 += __shfl_xor_sync(0xFFFFFFFFu, s2, o);
            }
            float mean = su * (1.0f / 128.0f);
            float var  = s2 * (1.0f / 128.0f) - mean * mean;
            float inv  = rsqrtf(var + EPS);

            v0 = (v0 - mean) * inv * gv.x + btv.x;
            v1 = (v1 - mean) * inv * gv.y + btv.y;
            v2 = (v2 - mean) * inv * gv.z + btv.z;
            v3 = (v3 - mean) * inv * gv.w + btv.w;
        }

        if (valid) {
            *reinterpret_cast<float4*>(out + (size_t)r * DNN + c0) =
                make_float4(v0, v1, v2, v3);
        }
    }
}

// ---------------------------------------------------------------------------
// Launch.  Inputs: in_feat[N,128] f32, edge_index[2,E] i32,
// W_rel[4,128,128], b_rel[4,128], W_root[4,128,128], ln_gamma[128],
// ln_beta[128].  Output: [N,128] f32.
// ---------------------------------------------------------------------------
extern "C" void kernel_launch(void* const* d_in, const int* in_sizes, int n_in,
                              void* d_out, int out_size)
{
    const float* in_feat = (const float*)d_in[0];
    const int*   ei      = (const int*)  d_in[1];
    const float* W_rel   = (const float*)d_in[2];
    const float* b_rel   = (const float*)d_in[3];
    const float* W_root  = (const float*)d_in[4];
    const float* gamma   = (const float*)d_in[5];
    const float* beta    = (const float*)d_in[6];
    float* out = (float*)d_out;

    const int Nn = in_sizes[0] / DNN;
    const int E  = in_sizes[1] / 2;
    const int* src = ei;
    const int* dst = ei + E;

    float *h0, *h1;
    int *deg, *off, *cur, *esrc;
    uint32_t *whi, *wlo;
    cudaGetSymbolAddress((void**)&h0,   g_h0);
    cudaGetSymbolAddress((void**)&h1,   g_h1);
    cudaGetSymbolAddress((void**)&deg,  g_deg);
    cudaGetSymbolAddress((void**)&off,  g_off);
    cudaGetSymbolAddress((void**)&cur,  g_cursor);
    cudaGetSymbolAddress((void**)&esrc, g_esrc);
    cudaGetSymbolAddress((void**)&whi,  g_whi);
    cudaGetSymbolAddress((void**)&wlo,  g_wlo);

    cudaFuncSetAttribute(conv_fused<0>,
                         cudaFuncAttributeMaxDynamicSharedMemorySize, CONV_SMEM);
    cudaFuncSetAttribute(conv_fused<1>,
                         cudaFuncAttributeMaxDynamicSharedMemorySize, CONV_SMEM);
    cudaFuncSetAttribute(conv_fused<2>,
                         cudaFuncAttributeMaxDynamicSharedMemorySize, CONV_SMEM);

    const int edgeBlocks = (E + 255) / 256;
    const int convBlocks = (Nn + 63) / 64;
    const size_t WPL     = (size_t)128 * WPSTRIDE;    // per-layer packed stride

    // ---- W split (once) + CSR build (once) ----
    wsplit_kernel<<<(4 * 128 * 128 + 255) / 256, 256>>>(W_rel, W_root, whi, wlo);
    cudaMemsetAsync(deg, 0, (size_t)(Nn + 1) * sizeof(int));
    hist_kernel<<<edgeBlocks, 256>>>(dst, deg, E);
    scan_kernel<<<1, 1024>>>(deg, off, cur, Nn, E);
    reorder_kernel<<<edgeBlocks, 256>>>(src, dst, cur, esrc, E);

    // ---- Layer 0: conv(in_feat) -> relu -> LN  => h0 ----
    conv_fused<0><<<convBlocks, 256, CONV_SMEM>>>(
        in_feat, esrc, off, whi + 0 * WPL, wlo + 0 * WPL,
        b_rel + 0 * DNN, gamma, beta, h0, Nn);

    // ---- Layer 1: conv(h0) + h0 -> relu -> LN  => h1 ----
    conv_fused<1><<<convBlocks, 256, CONV_SMEM>>>(
        h0, esrc, off, whi + 1 * WPL, wlo + 1 * WPL,
        b_rel + 1 * DNN, gamma, beta, h1, Nn);

    // ---- Layer 2: conv(h1) + h1 -> relu -> LN  => h0 ----
    conv_fused<1><<<convBlocks, 256, CONV_SMEM>>>(
        h1, esrc, off, whi + 2 * WPL, wlo + 2 * WPL,
        b_rel + 2 * DNN, gamma, beta, h0, Nn);

    // ---- Layer 3 (output): conv(h0) only => d_out ----
    conv_fused<2><<<convBlocks, 256, CONV_SMEM>>>(
        h0, esrc, off, whi + 3 * WPL, wlo + 3 * WPL,
        b_rel + 3 * DNN, gamma, beta, out, Nn);
}

// round 13
// speedup vs baseline: 1.1777x; 1.1777x over previous
#include <cuda_runtime.h>
#include <cuda_bf16.h>
#include <cstdint>

// Problem constants: N=100000 nodes, E=1600000 edges, D=128, L=4
#define DNN   128
#define MAXN  100000
#define MAXE  1600000
#define EPS   1e-5f

// Static device scratch (no cudaMalloc anywhere)
__device__ float    g_agg[(size_t)MAXN * DNN];
__device__ float    g_h0 [(size_t)MAXN * DNN];
__device__ float    g_h1 [(size_t)MAXN * DNN];
__device__ int      g_deg   [MAXN + 1];
__device__ int      g_off   [MAXN + 1];
__device__ int      g_cursor[MAXN + 1];
__device__ int      g_esrc  [MAXE];
// Pre-split weights: [4 layers][128 k-pairs][136 cols] packed bf16x2 (hi & lo)
#define WPSTRIDE 136
__device__ uint32_t g_whi[4 * 128 * WPSTRIDE];
__device__ uint32_t g_wlo[4 * 128 * WPSTRIDE];

// ---------------------------------------------------------------------------
// bf16 split: x ~= hi + lo. pack2: element a (even k) LOW half, b HIGH half.
// ---------------------------------------------------------------------------
__device__ __forceinline__ void bfsplit2(float a, float b,
                                         uint32_t& hi, uint32_t& lo)
{
    __nv_bfloat16 ah = __float2bfloat16(a);
    __nv_bfloat16 bh = __float2bfloat16(b);
    float ar = a - __bfloat162float(ah);
    float br = b - __bfloat162float(bh);
    __nv_bfloat16 al = __float2bfloat16(ar);
    __nv_bfloat16 bl = __float2bfloat16(br);
    hi = ((uint32_t)__bfloat16_as_ushort(bh) << 16) | __bfloat16_as_ushort(ah);
    lo = ((uint32_t)__bfloat16_as_ushort(bl) << 16) | __bfloat16_as_ushort(al);
}

// ---------------------------------------------------------------------------
// W pre-split: stacked K layout [W_rel(128) ; W_root(128)] per layer.
// ---------------------------------------------------------------------------
__global__ __launch_bounds__(256)
void wsplit_kernel(const float* __restrict__ Wrel,
                   const float* __restrict__ Wroot,
                   uint32_t* __restrict__ whi,
                   uint32_t* __restrict__ wlo)
{
    int idx = blockIdx.x * 256 + threadIdx.x;     // 0 .. 4*128*128-1
    if (idx >= 4 * 128 * 128) return;
    int c = idx & 127;
    int p = (idx >> 7) & 127;                     // k-pair 0..127
    int l = idx >> 14;                            // layer

    int k0 = 2 * p;
    float v0, v1;
    if (p < 64) {
        v0 = Wrel[(size_t)l * 16384 + k0 * 128 + c];
        v1 = Wrel[(size_t)l * 16384 + (k0 + 1) * 128 + c];
    } else {
        v0 = Wroot[(size_t)l * 16384 + (k0 - 128) * 128 + c];
        v1 = Wroot[(size_t)l * 16384 + (k0 - 127) * 128 + c];
    }
    uint32_t hi, lo;
    bfsplit2(v0, v1, hi, lo);
    size_t o = ((size_t)l * 128 + p) * WPSTRIDE + c;
    whi[o] = hi;
    wlo[o] = lo;
}

// ---------------------------------------------------------------------------
// CSR build: histogram of dst -> exclusive scan -> reorder src by dst bucket.
// ---------------------------------------------------------------------------
__global__ __launch_bounds__(256)
void hist_kernel(const int* __restrict__ dst, int* __restrict__ deg, int E)
{
    int e = blockIdx.x * blockDim.x + threadIdx.x;
    if (e < E) atomicAdd(&deg[dst[e]], 1);
}

__global__ __launch_bounds__(1024)
void scan_kernel(const int* __restrict__ deg, int* __restrict__ off,
                 int* __restrict__ cur, int Nn, int E)
{
    __shared__ int part[1024];
    const int tid   = threadIdx.x;
    const int chunk = (Nn + 1023) / 1024;
    const int s0    = tid * chunk;
    const int s1    = min(s0 + chunk, Nn);

    int sum = 0;
    for (int i = s0; i < s1; i++) sum += deg[i];
    part[tid] = sum;
    __syncthreads();

    for (int stp = 1; stp < 1024; stp <<= 1) {
        int v = (tid >= stp) ? part[tid - stp] : 0;
        __syncthreads();
        part[tid] += v;
        __syncthreads();
    }
    int base = (tid == 0) ? 0 : part[tid - 1];

    for (int i = s0; i < s1; i++) {
        off[i] = base;
        cur[i] = base;
        base  += deg[i];
    }
    if (tid == 0) off[Nn] = E;
}

__global__ __launch_bounds__(256)
void reorder_kernel(const int* __restrict__ src, const int* __restrict__ dst,
                    int* __restrict__ cur, int* __restrict__ esrc, int E)
{
    int e = blockIdx.x * blockDim.x + threadIdx.x;
    if (e >= E) return;
    int pos = atomicAdd(&cur[dst[e]], 1);
    esrc[pos] = src[e];
}

// ---------------------------------------------------------------------------
// Gather aggregation, MLP-4: agg[n] = sum over in-neighbors of h[src].
// One warp per node; edge loop unrolled 4-wide so 4 independent row loads
// are in flight before any accumulate (raises MLP 1 -> 4).
// ---------------------------------------------------------------------------
__global__ __launch_bounds__(256)
void gather_kernel(const float* __restrict__ h,
                   const int* __restrict__ esrc,
                   const int* __restrict__ off,
                   float* __restrict__ agg,
                   int Nn)
{
    int node = blockIdx.x * (blockDim.x >> 5) + (threadIdx.x >> 5);
    int lane = threadIdx.x & 31;
    if (node >= Nn) return;

    int b = off[node];
    int e = off[node + 1];

    float4 acc0 = make_float4(0.f, 0.f, 0.f, 0.f);
    float4 acc1 = make_float4(0.f, 0.f, 0.f, 0.f);

    int i = b;
    for (; i + 3 < e; i += 4) {
        int s0 = esrc[i    ];
        int s1 = esrc[i + 1];
        int s2 = esrc[i + 2];
        int s3 = esrc[i + 3];
        float4 v0 = reinterpret_cast<const float4*>(h + (size_t)s0 * DNN)[lane];
        float4 v1 = reinterpret_cast<const float4*>(h + (size_t)s1 * DNN)[lane];
        float4 v2 = reinterpret_cast<const float4*>(h + (size_t)s2 * DNN)[lane];
        float4 v3 = reinterpret_cast<const float4*>(h + (size_t)s3 * DNN)[lane];
        acc0.x += v0.x; acc0.y += v0.y; acc0.z += v0.z; acc0.w += v0.w;
        acc1.x += v1.x; acc1.y += v1.y; acc1.z += v1.z; acc1.w += v1.w;
        acc0.x += v2.x; acc0.y += v2.y; acc0.z += v2.z; acc0.w += v2.w;
        acc1.x += v3.x; acc1.y += v3.y; acc1.z += v3.z; acc1.w += v3.w;
    }
    for (; i < e; i++) {
        int s = esrc[i];
        float4 v = reinterpret_cast<const float4*>(h + (size_t)s * DNN)[lane];
        acc0.x += v.x; acc0.y += v.y; acc0.z += v.z; acc0.w += v.w;
    }
    acc0.x += acc1.x; acc0.y += acc1.y; acc0.z += acc1.z; acc0.w += acc1.w;
    reinterpret_cast<float4*>(agg + (size_t)node * DNN)[lane] = acc0;
}

// ---------------------------------------------------------------------------
// bf16 m16n8k16 MMA (A row-major, B col-major, f32 accum)
// ---------------------------------------------------------------------------
#define MMA_BF16(d, a, b)                                                     \
    asm volatile(                                                             \
        "mma.sync.aligned.m16n8k16.row.col.f32.bf16.bf16.f32 "                \
        "{%0,%1,%2,%3},{%4,%5,%6,%7},{%8,%9},{%0,%1,%2,%3};"                  \
        : "+f"((d)[0]), "+f"((d)[1]), "+f"((d)[2]), "+f"((d)[3])              \
        : "r"((a)[0]), "r"((a)[1]), "r"((a)[2]), "r"((a)[3]),                 \
          "r"((b)[0]), "r"((b)[1]))

// Shared-memory layout (dynamic; 53248 bytes > 48KB static limit)
struct ConvSM {
    uint32_t xh[64][36];    // X packed hi: stride 36 -> bank 4qr+qc, CF
    uint32_t xl[64][36];
    uint32_t wh[32][136];   // W packed hi: stride 136 -> bank 8qc+qr, CF
    uint32_t wl[32][136];
};
#define CONV_SMEM_BYTES (sizeof(ConvSM))   // 53248

// ---------------------------------------------------------------------------
// bf16 3-pass compensated conv layer (R8-proven core):
//   out = [agg | h] @ [[W_rel],[W_root]] + b_rel     (K=256, Ncols=128)
// MODE 0: relu -> LN     MODE 1: +h -> relu -> LN     MODE 2: plain
// ---------------------------------------------------------------------------
template <int MODE>
__global__ __launch_bounds__(256)
void conv_bf_kernel(const float* __restrict__ agg,
                    const float* __restrict__ hin,
                    const uint32_t* __restrict__ whi,  // [128 kp][136]
                    const uint32_t* __restrict__ wlo,
                    const float* __restrict__ br,
                    const float* __restrict__ gamma,
                    const float* __restrict__ beta,
                    float* __restrict__ out,
                    int Nn)
{
    extern __shared__ char smraw[];
    ConvSM& s = *reinterpret_cast<ConvSM*>(smraw);
    float (*ob)[132] = reinterpret_cast<float(*)[132]>(smraw);  // epilogue overlay

    const int tid  = threadIdx.x;
    const int lane = tid & 31;
    const int wid  = tid >> 5;
    const int wr   = wid >> 2;       // warp row: 0..1
    const int wc   = wid & 3;        // warp col: 0..3
    const int rowBase = blockIdx.x * 64;
    const int qr = lane >> 2;        // 0..7
    const int qc = lane & 3;         // 0..3

    float acc[2][4][4];
#pragma unroll
    for (int m = 0; m < 2; m++)
#pragma unroll
        for (int n = 0; n < 4; n++)
#pragma unroll
            for (int j = 0; j < 4; j++) acc[m][n][j] = 0.0f;

#pragma unroll
    for (int kt = 0; kt < 4; kt++) {
        // X source for this 64-wide k slice: stages 0,1 -> agg; 2,3 -> hin
        const float* xbase = (kt < 2) ? (agg + kt * 64)
                                      : (hin + (kt - 2) * 64);

        // ---- load X tile (64 rows x 64 k) as packed bf16x2 hi/lo ----
#pragma unroll
        for (int p = 0; p < 4; p++) {
            int cidx = tid + p * 256;         // 0..1023
            int m  = cidx >> 4;               // row 0..63
            int kq = cidx & 15;               // float4 chunk 0..15
            int r  = rowBase + m;
            float4 v = (r < Nn)
                ? *reinterpret_cast<const float4*>(xbase + (size_t)r * DNN + kq * 4)
                : make_float4(0.f, 0.f, 0.f, 0.f);
            uint32_t h0, l0, h1, l1;
            bfsplit2(v.x, v.y, h0, l0);
            bfsplit2(v.z, v.w, h1, l1);
            s.xh[m][kq * 2]     = h0;
            s.xl[m][kq * 2]     = l0;
            s.xh[m][kq * 2 + 1] = h1;
            s.xl[m][kq * 2 + 1] = l1;
        }

        // ---- load W tile (32 k-pairs x 128 cols), straight uint4 copy ----
#pragma unroll
        for (int p = 0; p < 4; p++) {
            int q  = tid + p * 256;           // 0..1023
            int kp = q >> 5;                  // 0..31
            int c4 = (q & 31) * 4;            // 0..124
            size_t go = (size_t)(kt * 32 + kp) * WPSTRIDE + c4;
            *reinterpret_cast<uint4*>(&s.wh[kp][c4]) =
                *reinterpret_cast<const uint4*>(whi + go);
            *reinterpret_cast<uint4*>(&s.wl[kp][c4]) =
                *reinterpret_cast<const uint4*>(wlo + go);
        }

        __syncthreads();

        // ---- 4 k16 substeps ----
#pragma unroll
        for (int ks = 0; ks < 4; ks++) {
            const int kp0 = ks * 8;

            uint32_t Ah[2][4], Al[2][4], Bh[4][2], Bl[4][2];
#pragma unroll
            for (int m = 0; m < 2; m++) {
                int r = wr * 32 + m * 16 + qr;
                Ah[m][0] = s.xh[r    ][kp0 + qc    ];
                Ah[m][1] = s.xh[r + 8][kp0 + qc    ];
                Ah[m][2] = s.xh[r    ][kp0 + qc + 4];
                Ah[m][3] = s.xh[r + 8][kp0 + qc + 4];
                Al[m][0] = s.xl[r    ][kp0 + qc    ];
                Al[m][1] = s.xl[r + 8][kp0 + qc    ];
                Al[m][2] = s.xl[r    ][kp0 + qc + 4];
                Al[m][3] = s.xl[r + 8][kp0 + qc + 4];
            }
#pragma unroll
            for (int n = 0; n < 4; n++) {
                int col = wc * 32 + n * 8 + qr;
                Bh[n][0] = s.wh[kp0 + qc    ][col];
                Bh[n][1] = s.wh[kp0 + qc + 4][col];
                Bl[n][0] = s.wl[kp0 + qc    ][col];
                Bl[n][1] = s.wl[kp0 + qc + 4][col];
            }

#pragma unroll
            for (int m = 0; m < 2; m++)
#pragma unroll
                for (int n = 0; n < 4; n++) {
                    MMA_BF16(acc[m][n], Ah[m], Bh[n]);
                    MMA_BF16(acc[m][n], Ah[m], Bl[n]);
                    MMA_BF16(acc[m][n], Al[m], Bh[n]);
                }
        }

        __syncthreads();
    }

    // ---- epilogue: acc -> smem (overlay), then per-row LayerNorm ----
#pragma unroll
    for (int m = 0; m < 2; m++) {
        int r0 = wr * 32 + m * 16 + qr;
#pragma unroll
        for (int n = 0; n < 4; n++) {
            int c = wc * 32 + n * 8 + qc * 2;
            ob[r0    ][c    ] = acc[m][n][0];
            ob[r0    ][c + 1] = acc[m][n][1];
            ob[r0 + 8][c    ] = acc[m][n][2];
            ob[r0 + 8][c + 1] = acc[m][n][3];
        }
    }
    __syncthreads();

    // Warp wid handles rows wid*8 .. wid*8+7; lane holds 4 cols (lane*4).
    const int c0 = lane * 4;
    const float4 bv = *reinterpret_cast<const float4*>(br + c0);
    float4 gv, btv;
    if (MODE < 2) {
        gv  = *reinterpret_cast<const float4*>(gamma + c0);
        btv = *reinterpret_cast<const float4*>(beta  + c0);
    }

#pragma unroll
    for (int i = 0; i < 8; i++) {
        int lr = wid * 8 + i;
        int r  = rowBase + lr;
        bool valid = (r < Nn);

        float4 v = *reinterpret_cast<const float4*>(&ob[lr][c0]);
        float v0 = v.x + bv.x;
        float v1 = v.y + bv.y;
        float v2 = v.z + bv.z;
        float v3 = v.w + bv.w;

        if (MODE == 1) {
            if (valid) {
                float4 hr = *reinterpret_cast<const float4*>(hin + (size_t)r * DNN + c0);
                v0 += hr.x; v1 += hr.y; v2 += hr.z; v3 += hr.w;
            }
        }

        if (MODE < 2) {
            v0 = fmaxf(v0, 0.0f);
            v1 = fmaxf(v1, 0.0f);
            v2 = fmaxf(v2, 0.0f);
            v3 = fmaxf(v3, 0.0f);

            float su = v0 + v1 + v2 + v3;
            float s2 = v0 * v0 + v1 * v1 + v2 * v2 + v3 * v3;
#pragma unroll
            for (int off = 16; off >= 1; off >>= 1) {
                su += __shfl_xor_sync(0xFFFFFFFFu, su, off);
                s2 += __shfl_xor_sync(0xFFFFFFFFu, s2, off);
            }
            float mean = su * (1.0f / 128.0f);
            float var  = s2 * (1.0f / 128.0f) - mean * mean;
            float inv  = rsqrtf(var + EPS);

            v0 = (v0 - mean) * inv * gv.x + btv.x;
            v1 = (v1 - mean) * inv * gv.y + btv.y;
            v2 = (v2 - mean) * inv * gv.z + btv.z;
            v3 = (v3 - mean) * inv * gv.w + btv.w;
        }

        if (valid) {
            *reinterpret_cast<float4*>(out + (size_t)r * DNN + c0) =
                make_float4(v0, v1, v2, v3);
        }
    }
}

// ---------------------------------------------------------------------------
// Launch.  Inputs: in_feat[N,128] f32, edge_index[2,E] i32,
// W_rel[4,128,128], b_rel[4,128], W_root[4,128,128], ln_gamma[128],
// ln_beta[128].  Output: [N,128] f32.
// ---------------------------------------------------------------------------
extern "C" void kernel_launch(void* const* d_in, const int* in_sizes, int n_in,
                              void* d_out, int out_size)
{
    const float* in_feat = (const float*)d_in[0];
    const int*   ei      = (const int*)  d_in[1];
    const float* W_rel   = (const float*)d_in[2];
    const float* b_rel   = (const float*)d_in[3];
    const float* W_root  = (const float*)d_in[4];
    const float* gamma   = (const float*)d_in[5];
    const float* beta    = (const float*)d_in[6];
    float* out = (float*)d_out;

    const int Nn = in_sizes[0] / DNN;
    const int E  = in_sizes[1] / 2;
    const int* src = ei;
    const int* dst = ei + E;

    float *agg, *h0, *h1;
    int *deg, *off, *cur, *esrc;
    uint32_t *whi, *wlo;
    cudaGetSymbolAddress((void**)&agg,  g_agg);
    cudaGetSymbolAddress((void**)&h0,   g_h0);
    cudaGetSymbolAddress((void**)&h1,   g_h1);
    cudaGetSymbolAddress((void**)&deg,  g_deg);
    cudaGetSymbolAddress((void**)&off,  g_off);
    cudaGetSymbolAddress((void**)&cur,  g_cursor);
    cudaGetSymbolAddress((void**)&esrc, g_esrc);
    cudaGetSymbolAddress((void**)&whi,  g_whi);
    cudaGetSymbolAddress((void**)&wlo,  g_wlo);

    // Allow >48KB dynamic smem for the conv kernels (idempotent, capture-safe)
    cudaFuncSetAttribute(conv_bf_kernel<0>,
                         cudaFuncAttributeMaxDynamicSharedMemorySize, CONV_SMEM_BYTES);
    cudaFuncSetAttribute(conv_bf_kernel<1>,
                         cudaFuncAttributeMaxDynamicSharedMemorySize, CONV_SMEM_BYTES);
    cudaFuncSetAttribute(conv_bf_kernel<2>,
                         cudaFuncAttributeMaxDynamicSharedMemorySize, CONV_SMEM_BYTES);

    const int edgeBlocks   = (E + 255) / 256;
    const int gatherBlocks = (Nn + 7) / 8;
    const int convBlocks   = (Nn + 63) / 64;
    const size_t WPL       = (size_t)128 * WPSTRIDE;   // per-layer packed stride

    // ---- W split (once) + CSR build (once) ----
    wsplit_kernel<<<(4 * 128 * 128 + 255) / 256, 256>>>(W_rel, W_root, whi, wlo);
    cudaMemsetAsync(deg, 0, (size_t)(Nn + 1) * sizeof(int));
    hist_kernel<<<edgeBlocks, 256>>>(dst, deg, E);
    scan_kernel<<<1, 1024>>>(deg, off, cur, Nn, E);
    reorder_kernel<<<edgeBlocks, 256>>>(src, dst, cur, esrc, E);

    // ---- Layer 0: conv(in_feat) -> relu -> LN  => h0 ----
    gather_kernel<<<gatherBlocks, 256>>>(in_feat, esrc, off, agg, Nn);
    conv_bf_kernel<0><<<convBlocks, 256, CONV_SMEM_BYTES>>>(
        agg, in_feat, whi + 0 * WPL, wlo + 0 * WPL,
        b_rel + 0 * DNN, gamma, beta, h0, Nn);

    // ---- Layer 1: conv(h0) + h0 -> relu -> LN  => h1 ----
    gather_kernel<<<gatherBlocks, 256>>>(h0, esrc, off, agg, Nn);
    conv_bf_kernel<1><<<convBlocks, 256, CONV_SMEM_BYTES>>>(
        agg, h0, whi + 1 * WPL, wlo + 1 * WPL,
        b_rel + 1 * DNN, gamma, beta, h1, Nn);

    // ---- Layer 2: conv(h1) + h1 -> relu -> LN  => h0 ----
    gather_kernel<<<gatherBlocks, 256>>>(h1, esrc, off, agg, Nn);
    conv_bf_kernel<1><<<convBlocks, 256, CONV_SMEM_BYTES>>>(
        agg, h1, whi + 2 * WPL, wlo + 2 * WPL,
        b_rel + 2 * DNN, gamma, beta, h0, Nn);

    // ---- Layer 3 (output): conv(h0) only => d_out ----
    gather_kernel<<<gatherBlocks, 256>>>(h0, esrc, off, agg, Nn);
    conv_bf_kernel<2><<<convBlocks, 256, CONV_SMEM_BYTES>>>(
        agg, h0, whi + 3 * WPL, wlo + 3 * WPL,
        b_rel + 3 * DNN, gamma, beta, out, Nn);
}